// round 7
// baseline (speedup 1.0000x reference)
#include <cuda_runtime.h>

// Problem constants (fixed shapes from reference setup_inputs)
#define BB   2
#define CC   32
#define HH   47
#define WW   156
#define DD   120
#define DP1  121              // D+1 softmax channels
#define HW   (HH * WW)        // 7332
#define QW   (HW / 4)         // 1833 float4s per (h,w) plane
#define NPIX (BB * HW)        // 14664
#define NFF  (BB * CC * DD * HW)  // 56,309,760 elements per frustum tensor
#define HP   (HH * 8)         // 376
#define WP   (WW * 8)         // 1248
#define DQ   (DD / 4)         // 30 d-slabs of 4
#define CG   2                // c-groups in kernel A
#define CPG  (CC / CG)        // 16 channels per group

// Fused prep kernel block ranges
#define DENOM_BLOCKS ((NPIX + 31) / 32)            // 459 (32 pixels/block)
#define POOL_BLOCKS  ((NPIX + 511) / 512)          // 29
#define PREP_BLOCKS  (DENOM_BLOCKS + POOL_BLOCKS)  // 488

// Scratch: per-pixel inverse softmax denominators (59 KB).
__device__ float g_inv[NPIX];

// ---------------------------------------------------------------------------
// K1 (fused): softmax denominators + sparse 8x8 pool, dispatched by blockIdx.
// ---------------------------------------------------------------------------
__global__ void __launch_bounds__(512) prep_kernel(
    const float* __restrict__ logits,
    const float* __restrict__ dm,
    float*       __restrict__ out)
{
    int t = threadIdx.x;

    if (blockIdx.x < DENOM_BLOCKS) {
        // ---------------- softmax denominators ----------------
        __shared__ float part[32][16];
        int pl = t & 31;           // pixel within block
        int q  = t >> 5;           // channel-chunk 0..15
        int p  = blockIdx.x * 32 + pl;

        float s = 0.f;
        if (p < NPIX) {
            int b   = p / HW;
            int rem = p - b * HW;
            const float* base = logits + (size_t)b * DP1 * HW + rem;
            int c0 = q * 8;
            int c1 = c0 + 8; if (c1 > DP1) c1 = DP1;   // q==15 covers 120 only
            #pragma unroll
            for (int ch = 0; ch < 8; ch++) {
                if (c0 + ch < c1)
                    s += __expf(base[(size_t)(c0 + ch) * HW]);
            }
        }
        part[pl][q] = s;
        __syncthreads();
        if (q == 0 && p < NPIX) {
            float tot = 0.f;
            #pragma unroll
            for (int i = 0; i < 16; i++) tot += part[pl][i];
            g_inv[p] = 1.0f / tot;
        }
    } else {
        // ---------------- sparse 8x8 average pool ----------------
        int p = (blockIdx.x - DENOM_BLOCKS) * 512 + t;
        if (p >= NPIX) return;
        int b   = p / HW;
        int rem = p - b * HW;
        int h   = rem / WW;
        int w   = rem - h * WW;

        const float* base = dm + ((size_t)b * HP + (size_t)h * 8) * WP + (size_t)w * 8;

        float sum = 0.f;
        float cnt = 0.f;
        #pragma unroll
        for (int i = 0; i < 8; i++) {
            const float4* row = reinterpret_cast<const float4*>(base + (size_t)i * WP);
            float4 v0 = row[0];
            float4 v1 = row[1];
            sum += (v0.x + v0.y) + (v0.z + v0.w) + (v1.x + v1.y) + (v1.z + v1.w);
            cnt += (v0.x != 0.f) + (v0.y != 0.f) + (v0.z != 0.f) + (v0.w != 0.f)
                 + (v1.x != 0.f) + (v1.y != 0.f) + (v1.z != 0.f) + (v1.w != 0.f);
        }
        float a  = sum * (1.0f / 64.0f);
        float bf = cnt * (1.0f / 64.0f);
        out[2 * (size_t)NFF + p] = a / (bf + 1e-10f);
    }
}

// ---------------------------------------------------------------------------
// K2 (A): fused softmax-apply -> frustum_features only.
// Thread = (b, c-group, d-slab of 4, p4): computes its 4x4 probs block in
// registers from logits, then loops 16 channels: 1 img float4 load (L2) and
// 4 streaming STG.128. No target work -> lower regs -> higher occupancy.
// ---------------------------------------------------------------------------
__global__ void __launch_bounds__(256, 5) frustumA_kernel(
    const float* __restrict__ logits,
    const float* __restrict__ img,
    float*       __restrict__ out)
{
    unsigned idx = blockIdx.x * blockDim.x + threadIdx.x;
    if (idx >= (unsigned)(BB * CG * DQ * QW)) return;
    unsigned p4 = idx % QW;
    unsigned r  = idx / QW;
    unsigned dq = r % DQ;
    r /= DQ;
    unsigned cg = r % CG;
    unsigned b  = r / CG;
    int d0 = dq * 4;
    int c0 = cg * CPG;

    float4 I = ((const float4*)g_inv)[(size_t)b * QW + p4];

    // Probs for the 4x4 (d, pixel) tile, computed in registers.
    float4 P[4];
    #pragma unroll
    for (int j = 0; j < 4; j++) {
        float4 L = ((const float4*)logits)[((size_t)b * DP1 + d0 + j) * QW + p4];
        P[j].x = __expf(L.x) * I.x;
        P[j].y = __expf(L.y) * I.y;
        P[j].z = __expf(L.z) * I.z;
        P[j].w = __expf(L.w) * I.w;
    }

    const float4* ig = (const float4*)img + ((size_t)b * CC + c0) * QW + p4;
    float4* ob = (float4*)out + (((size_t)b * CC + c0) * DD + d0) * QW + p4;
    const size_t cstride = (size_t)DD * QW;

    #pragma unroll 2
    for (int c = 0; c < CPG; c++) {
        float4 iv = ig[(size_t)c * QW];
        float4* o1 = ob + (size_t)c * cstride;
        #pragma unroll
        for (int j = 0; j < 4; j++) {
            float4 a;
            a.x = iv.x * P[j].x; a.y = iv.y * P[j].y;
            a.z = iv.z * P[j].z; a.w = iv.w * P[j].w;
            __stcs(&o1[(size_t)j * QW], a);
        }
    }
}

// ---------------------------------------------------------------------------
// K3 (B): frustum_features_target. One-hot over d: write 120 zero float4
// planes (pure store stream, no per-d ALU), then <=4 scalar fix-up stores at
// d = bin (same-thread program order guarantees the overwrite lands).
// ~20 regs, near-pure write streamer.
// ---------------------------------------------------------------------------
__global__ void __launch_bounds__(256) frustumB_kernel(
    const float* __restrict__ img,
    const int*   __restrict__ bins,
    float*       __restrict__ out)
{
    unsigned idx = blockIdx.x * blockDim.x + threadIdx.x;
    if (idx >= (unsigned)(BB * CC * QW)) return;
    unsigned p4 = idx % QW;
    unsigned r  = idx / QW;
    unsigned c  = r % CC;
    unsigned b  = r / CC;

    float4 iv = ((const float4*)img)[(size_t)(b * CC + c) * QW + p4];
    int4   bn = ((const int4*)bins)[(size_t)b * QW + p4];

    float4* o2 = (float4*)out + (size_t)NFF / 4
               + (size_t)(b * CC + c) * DD * QW + p4;

    const float4 z = make_float4(0.f, 0.f, 0.f, 0.f);
    #pragma unroll 8
    for (int d = 0; d < DD; d++)
        __stcs(&o2[(size_t)d * QW], z);

    // Scalar fix-ups: element base of this thread's 4 pixels.
    float* o2e = out + (size_t)NFF + (size_t)(b * CC + c) * DD * HW + 4 * p4;
    if (bn.x < DD) o2e[(size_t)bn.x * HW + 0] = iv.x;
    if (bn.y < DD) o2e[(size_t)bn.y * HW + 1] = iv.y;
    if (bn.z < DD) o2e[(size_t)bn.z * HW + 2] = iv.z;
    if (bn.w < DD) o2e[(size_t)bn.w * HW + 3] = iv.w;
}

// ---------------------------------------------------------------------------
// Launch contract
// Inputs: image_features f32, depth_logits f32, depth_maps f32,
//         depth_target_bin i32
// Output: [frustum_features | frustum_features_target | pooled_depth] f32
// ---------------------------------------------------------------------------
extern "C" void kernel_launch(void* const* d_in, const int* in_sizes, int n_in,
                              void* d_out, int out_size) {
    const float* image_features   = (const float*)d_in[0];
    const float* depth_logits     = (const float*)d_in[1];
    const float* depth_maps       = (const float*)d_in[2];
    const int*   depth_target_bin = (const int*)d_in[3];
    float* out = (float*)d_out;

    // Fused softmax denominators + sparse pool.
    prep_kernel<<<PREP_BLOCKS, 512>>>(depth_logits, depth_maps, out);

    // A: frustum_features (softmax-apply + multiply).
    {
        int total  = BB * CG * DQ * QW;          // 219,960
        int blocks = (total + 255) / 256;        // 860
        frustumA_kernel<<<blocks, 256>>>(depth_logits, image_features, out);
    }
    // B: frustum_features_target (one-hot streamer).
    {
        int total  = BB * CC * QW;               // 117,312
        int blocks = (total + 255) / 256;        // 459
        frustumB_kernel<<<blocks, 256>>>(image_features, depth_target_bin, out);
    }
}

// round 9
// speedup vs baseline: 1.3476x; 1.3476x over previous
#include <cuda_runtime.h>

// Problem constants (fixed shapes from reference setup_inputs)
#define BB   2
#define CC   32
#define HH   47
#define WW   156
#define DD   120
#define DP1  121              // D+1 softmax channels
#define HW   (HH * WW)        // 7332
#define QW   (HW / 4)         // 1833 float4s per (h,w) plane
#define NPIX (BB * HW)        // 14664
#define NFF  (BB * CC * DD * HW)  // 56,309,760 elements per frustum tensor
#define HP   (HH * 8)         // 376
#define WP   (WW * 8)         // 1248
#define DS   2                // d-slab size per thread
#define DQ2  (DD / DS)        // 60 d-slabs
#define CG   2                // c-groups in frustum kernel
#define CPG  (CC / CG)        // 16 channels per group

// Fused prep kernel block ranges
#define DENOM_BLOCKS ((NPIX + 31) / 32)            // 459 (32 pixels/block)
#define POOL_BLOCKS  ((NPIX + 511) / 512)          // 29
#define PREP_BLOCKS  (DENOM_BLOCKS + POOL_BLOCKS)  // 488

// Scratch: per-pixel inverse softmax denominators (59 KB).
__device__ float g_inv[NPIX];

// ---------------------------------------------------------------------------
// K1 (fused): softmax denominators + sparse 8x8 pool, dispatched by blockIdx.
// (unchanged from round 6 — measured 7.1us total for both halves)
// ---------------------------------------------------------------------------
__global__ void __launch_bounds__(512) prep_kernel(
    const float* __restrict__ logits,
    const float* __restrict__ dm,
    float*       __restrict__ out)
{
    int t = threadIdx.x;

    if (blockIdx.x < DENOM_BLOCKS) {
        // ---------------- softmax denominators ----------------
        __shared__ float part[32][16];
        int pl = t & 31;           // pixel within block
        int q  = t >> 5;           // channel-chunk 0..15
        int p  = blockIdx.x * 32 + pl;

        float s = 0.f;
        if (p < NPIX) {
            int b   = p / HW;
            int rem = p - b * HW;
            const float* base = logits + (size_t)b * DP1 * HW + rem;
            int c0 = q * 8;
            int c1 = c0 + 8; if (c1 > DP1) c1 = DP1;   // q==15 covers 120 only
            #pragma unroll
            for (int ch = 0; ch < 8; ch++) {
                if (c0 + ch < c1)
                    s += __expf(base[(size_t)(c0 + ch) * HW]);
            }
        }
        part[pl][q] = s;
        __syncthreads();
        if (q == 0 && p < NPIX) {
            float tot = 0.f;
            #pragma unroll
            for (int i = 0; i < 16; i++) tot += part[pl][i];
            g_inv[p] = 1.0f / tot;
        }
    } else {
        // ---------------- sparse 8x8 average pool ----------------
        int p = (blockIdx.x - DENOM_BLOCKS) * 512 + t;
        if (p >= NPIX) return;
        int b   = p / HW;
        int rem = p - b * HW;
        int h   = rem / WW;
        int w   = rem - h * WW;

        const float* base = dm + ((size_t)b * HP + (size_t)h * 8) * WP + (size_t)w * 8;

        float sum = 0.f;
        float cnt = 0.f;
        #pragma unroll
        for (int i = 0; i < 8; i++) {
            const float4* row = reinterpret_cast<const float4*>(base + (size_t)i * WP);
            float4 v0 = row[0];
            float4 v1 = row[1];
            sum += (v0.x + v0.y) + (v0.z + v0.w) + (v1.x + v1.y) + (v1.z + v1.w);
            cnt += (v0.x != 0.f) + (v0.y != 0.f) + (v0.z != 0.f) + (v0.w != 0.f)
                 + (v1.x != 0.f) + (v1.y != 0.f) + (v1.z != 0.f) + (v1.w != 0.f);
        }
        float a  = sum * (1.0f / 64.0f);
        float bf = cnt * (1.0f / 64.0f);
        out[2 * (size_t)NFF + p] = a / (bf + 1e-10f);
    }
}

// ---------------------------------------------------------------------------
// K2: fused softmax-apply + frustum writer (round-6 structure, SMALLER TILE).
// Thread = (b, c-group, d-slab of 2, p4): computes its 2x4 probs block in
// registers from logits, then loops 16 channels: 1 img float4 load (L2) and
// 4 streaming STG.128 (2 per output tensor). The d-tile reduction (4 -> 2)
// cuts live registers (P: 16 -> 8 regs) to raise the reg-limited occupancy
// ceiling from 4 blocks/SM toward 5-6, without any forced cap (plain
// launch_bounds: compiler keeps its natural allocation, no spills).
// ---------------------------------------------------------------------------
__global__ void __launch_bounds__(256) frustum_kernel(
    const float* __restrict__ logits,
    const float* __restrict__ img,
    const int*   __restrict__ bins,
    float*       __restrict__ out)
{
    unsigned idx = blockIdx.x * blockDim.x + threadIdx.x;
    if (idx >= (unsigned)(BB * CG * DQ2 * QW)) return;
    unsigned p4 = idx % QW;
    unsigned r  = idx / QW;
    unsigned dq = r % DQ2;
    r /= DQ2;
    unsigned cg = r % CG;
    unsigned b  = r / CG;
    int d0 = dq * DS;
    int c0 = cg * CPG;

    // Per-pixel inverse denominators and target bins.
    float4 I  = ((const float4*)g_inv)[(size_t)b * QW + p4];
    int4   bn = ((const int4*)bins)[(size_t)b * QW + p4];

    // Probs for the 2x4 (d, pixel) tile, computed in registers.
    float4 P[DS];
    #pragma unroll
    for (int j = 0; j < DS; j++) {
        float4 L = ((const float4*)logits)[((size_t)b * DP1 + d0 + j) * QW + p4];
        P[j].x = __expf(L.x) * I.x;
        P[j].y = __expf(L.y) * I.y;
        P[j].z = __expf(L.z) * I.z;
        P[j].w = __expf(L.w) * I.w;
    }

    const float4* ig = (const float4*)img + ((size_t)b * CC + c0) * QW + p4;
    float4* ob = (float4*)out + (((size_t)b * CC + c0) * DD + d0) * QW + p4;
    const size_t cstride = (size_t)DD * QW;
    const size_t osplit  = (size_t)NFF / 4;

    #pragma unroll 2
    for (int c = 0; c < CPG; c++) {
        float4 iv = ig[(size_t)c * QW];
        float4* o1 = ob + (size_t)c * cstride;
        float4* o2 = o1 + osplit;
        #pragma unroll
        for (int j = 0; j < DS; j++) {
            int d = d0 + j;
            float4 a;
            a.x = iv.x * P[j].x; a.y = iv.y * P[j].y;
            a.z = iv.z * P[j].z; a.w = iv.w * P[j].w;
            float4 t;
            t.x = (d == bn.x) ? iv.x : 0.0f;
            t.y = (d == bn.y) ? iv.y : 0.0f;
            t.z = (d == bn.z) ? iv.z : 0.0f;
            t.w = (d == bn.w) ? iv.w : 0.0f;
            __stcs(&o1[(size_t)j * QW], a);
            __stcs(&o2[(size_t)j * QW], t);
        }
    }
}

// ---------------------------------------------------------------------------
// Launch contract
// Inputs: image_features f32, depth_logits f32, depth_maps f32,
//         depth_target_bin i32
// Output: [frustum_features | frustum_features_target | pooled_depth] f32
// ---------------------------------------------------------------------------
extern "C" void kernel_launch(void* const* d_in, const int* in_sizes, int n_in,
                              void* d_out, int out_size) {
    const float* image_features   = (const float*)d_in[0];
    const float* depth_logits     = (const float*)d_in[1];
    const float* depth_maps       = (const float*)d_in[2];
    const int*   depth_target_bin = (const int*)d_in[3];
    float* out = (float*)d_out;

    // Fused softmax denominators + sparse pool.
    prep_kernel<<<PREP_BLOCKS, 512>>>(depth_logits, depth_maps, out);

    // Fused softmax-apply + frustum writer.
    {
        int total  = BB * CG * DQ2 * QW;         // 439,920
        int blocks = (total + 255) / 256;        // 1719
        frustum_kernel<<<blocks, 256>>>(depth_logits, image_features,
                                        depth_target_bin, out);
    }
}

// round 10
// speedup vs baseline: 1.4048x; 1.0424x over previous
#include <cuda_runtime.h>

// Problem constants (fixed shapes from reference setup_inputs)
#define BB   2
#define CC   32
#define HH   47
#define WW   156
#define DD   120
#define DP1  121              // D+1 softmax channels
#define HW   (HH * WW)        // 7332
#define QW   (HW / 4)         // 1833 float4s per (h,w) plane
#define NPIX (BB * HW)        // 14664
#define NFF  (BB * CC * DD * HW)  // 56,309,760 elements per frustum tensor
#define HP   (HH * 8)         // 376
#define WP   (WW * 8)         // 1248
#define DQ   (DD / 4)         // 30 d-slabs of 4
#define CG   4                // c-groups (was 2 in round 6): 1719 blocks, 2.9 waves
#define CPG  (CC / CG)        // 8 channels per group

// Fused prep kernel block ranges
#define DENOM_BLOCKS ((NPIX + 31) / 32)            // 459 (32 pixels/block)
#define POOL_BLOCKS  ((NPIX + 511) / 512)          // 29
#define PREP_BLOCKS  (DENOM_BLOCKS + POOL_BLOCKS)  // 488

// Scratch: per-pixel inverse softmax denominators (59 KB).
__device__ float g_inv[NPIX];

// ---------------------------------------------------------------------------
// K1 (fused): softmax denominators + sparse 8x8 pool, dispatched by blockIdx.
// (unchanged — measured ~7.1us for both halves)
// ---------------------------------------------------------------------------
__global__ void __launch_bounds__(512) prep_kernel(
    const float* __restrict__ logits,
    const float* __restrict__ dm,
    float*       __restrict__ out)
{
    int t = threadIdx.x;

    if (blockIdx.x < DENOM_BLOCKS) {
        // ---------------- softmax denominators ----------------
        __shared__ float part[32][16];
        int pl = t & 31;           // pixel within block
        int q  = t >> 5;           // channel-chunk 0..15
        int p  = blockIdx.x * 32 + pl;

        float s = 0.f;
        if (p < NPIX) {
            int b   = p / HW;
            int rem = p - b * HW;
            const float* base = logits + (size_t)b * DP1 * HW + rem;
            int c0 = q * 8;
            int c1 = c0 + 8; if (c1 > DP1) c1 = DP1;   // q==15 covers 120 only
            #pragma unroll
            for (int ch = 0; ch < 8; ch++) {
                if (c0 + ch < c1)
                    s += __expf(base[(size_t)(c0 + ch) * HW]);
            }
        }
        part[pl][q] = s;
        __syncthreads();
        if (q == 0 && p < NPIX) {
            float tot = 0.f;
            #pragma unroll
            for (int i = 0; i < 16; i++) tot += part[pl][i];
            g_inv[p] = 1.0f / tot;
        }
    } else {
        // ---------------- sparse 8x8 average pool ----------------
        int p = (blockIdx.x - DENOM_BLOCKS) * 512 + t;
        if (p >= NPIX) return;
        int b   = p / HW;
        int rem = p - b * HW;
        int h   = rem / WW;
        int w   = rem - h * WW;

        const float* base = dm + ((size_t)b * HP + (size_t)h * 8) * WP + (size_t)w * 8;

        float sum = 0.f;
        float cnt = 0.f;
        #pragma unroll
        for (int i = 0; i < 8; i++) {
            const float4* row = reinterpret_cast<const float4*>(base + (size_t)i * WP);
            float4 v0 = row[0];
            float4 v1 = row[1];
            sum += (v0.x + v0.y) + (v0.z + v0.w) + (v1.x + v1.y) + (v1.z + v1.w);
            cnt += (v0.x != 0.f) + (v0.y != 0.f) + (v0.z != 0.f) + (v0.w != 0.f)
                 + (v1.x != 0.f) + (v1.y != 0.f) + (v1.z != 0.f) + (v1.w != 0.f);
        }
        float a  = sum * (1.0f / 64.0f);
        float bf = cnt * (1.0f / 64.0f);
        out[2 * (size_t)NFF + p] = a / (bf + 1e-10f);
    }
}

// ---------------------------------------------------------------------------
// K2: fused softmax-apply + frustum writer. ROUND-6 per-thread tile (d-slab
// of 4, natural regs ~62, 4 blocks/SM) — the config that achieved 5.48 TB/s —
// with the c-dimension split into 4 groups of 8 instead of 2 of 16.
// Grid: 1719 blocks -> 2.90 waves at 4/SM -> ~97% wave packing (vs 73% at
// 860 blocks). Single-variable experiment: packing vs write-BW wall.
// ---------------------------------------------------------------------------
__global__ void __launch_bounds__(256) frustum_kernel(
    const float* __restrict__ logits,
    const float* __restrict__ img,
    const int*   __restrict__ bins,
    float*       __restrict__ out)
{
    unsigned idx = blockIdx.x * blockDim.x + threadIdx.x;
    if (idx >= (unsigned)(BB * CG * DQ * QW)) return;
    unsigned p4 = idx % QW;
    unsigned r  = idx / QW;
    unsigned dq = r % DQ;
    r /= DQ;
    unsigned cg = r % CG;
    unsigned b  = r / CG;
    int d0 = dq * 4;
    int c0 = cg * CPG;

    // Per-pixel inverse denominators and target bins.
    float4 I  = ((const float4*)g_inv)[(size_t)b * QW + p4];
    int4   bn = ((const int4*)bins)[(size_t)b * QW + p4];

    // Probs for the 4x4 (d, pixel) tile, computed in registers.
    float4 P[4];
    #pragma unroll
    for (int j = 0; j < 4; j++) {
        float4 L = ((const float4*)logits)[((size_t)b * DP1 + d0 + j) * QW + p4];
        P[j].x = __expf(L.x) * I.x;
        P[j].y = __expf(L.y) * I.y;
        P[j].z = __expf(L.z) * I.z;
        P[j].w = __expf(L.w) * I.w;
    }

    const float4* ig = (const float4*)img + ((size_t)b * CC + c0) * QW + p4;
    float4* ob = (float4*)out + (((size_t)b * CC + c0) * DD + d0) * QW + p4;
    const size_t cstride = (size_t)DD * QW;
    const size_t osplit  = (size_t)NFF / 4;

    #pragma unroll 2
    for (int c = 0; c < CPG; c++) {
        float4 iv = ig[(size_t)c * QW];
        float4* o1 = ob + (size_t)c * cstride;
        float4* o2 = o1 + osplit;
        #pragma unroll
        for (int j = 0; j < 4; j++) {
            int d = d0 + j;
            float4 a;
            a.x = iv.x * P[j].x; a.y = iv.y * P[j].y;
            a.z = iv.z * P[j].z; a.w = iv.w * P[j].w;
            float4 t;
            t.x = (d == bn.x) ? iv.x : 0.0f;
            t.y = (d == bn.y) ? iv.y : 0.0f;
            t.z = (d == bn.z) ? iv.z : 0.0f;
            t.w = (d == bn.w) ? iv.w : 0.0f;
            __stcs(&o1[(size_t)j * QW], a);
            __stcs(&o2[(size_t)j * QW], t);
        }
    }
}

// ---------------------------------------------------------------------------
// Launch contract
// Inputs: image_features f32, depth_logits f32, depth_maps f32,
//         depth_target_bin i32
// Output: [frustum_features | frustum_features_target | pooled_depth] f32
// ---------------------------------------------------------------------------
extern "C" void kernel_launch(void* const* d_in, const int* in_sizes, int n_in,
                              void* d_out, int out_size) {
    const float* image_features   = (const float*)d_in[0];
    const float* depth_logits     = (const float*)d_in[1];
    const float* depth_maps       = (const float*)d_in[2];
    const int*   depth_target_bin = (const int*)d_in[3];
    float* out = (float*)d_out;

    // Fused softmax denominators + sparse pool.
    prep_kernel<<<PREP_BLOCKS, 512>>>(depth_logits, depth_maps, out);

    // Fused softmax-apply + frustum writer.
    {
        int total  = BB * CG * DQ * QW;          // 439,920
        int blocks = (total + 255) / 256;        // 1719
        frustum_kernel<<<blocks, 256>>>(depth_logits, image_features,
                                        depth_target_bin, out);
    }
}

// round 11
// speedup vs baseline: 1.4319x; 1.0193x over previous
#include <cuda_runtime.h>

// Problem constants (fixed shapes from reference setup_inputs)
#define BB   2
#define CC   32
#define HH   47
#define WW   156
#define DD   120
#define DP1  121              // D+1 softmax channels
#define HW   (HH * WW)        // 7332
#define QW   (HW / 4)         // 1833 float4s per (h,w) plane
#define NPIX (BB * HW)        // 14664
#define NFF  (BB * CC * DD * HW)  // 56,309,760 elements per frustum tensor
#define HP   (HH * 8)         // 376
#define WP   (WW * 8)         // 1248
#define DQ   (DD / 4)         // 30 d-slabs of 4
#define CG   4                // c-groups: round-10 best (81.4us frustum)
#define CPG  (CC / CG)        // 8 channels per group

#define DENOM_BLOCKS ((NPIX + 31) / 32)            // 459 (32 pixels/block)

// Frustum+pool fused launch: frustum blocks first, pool blocks appended.
#define FRUST_BLOCKS ((BB * CG * DQ * QW + 255) / 256)  // 1719
#define POOL_BLOCKS  ((NPIX + 255) / 256)               // 58
#define MAIN_BLOCKS  (FRUST_BLOCKS + POOL_BLOCKS)       // 1777

// Scratch: per-pixel inverse softmax denominators (59 KB).
__device__ float g_inv[NPIX];

// ---------------------------------------------------------------------------
// K1: softmax denominators only (pool moved into the main kernel).
// 512 threads = 32 pixels x 16 channel-chunks of ~8; warp = 32 consecutive
// pixels at one channel -> perfect 128B coalescing.
// ---------------------------------------------------------------------------
__global__ void __launch_bounds__(512) denom_kernel(
    const float* __restrict__ logits)
{
    __shared__ float part[32][16];
    int t  = threadIdx.x;
    int pl = t & 31;           // pixel within block
    int q  = t >> 5;           // channel-chunk 0..15
    int p  = blockIdx.x * 32 + pl;

    float s = 0.f;
    if (p < NPIX) {
        int b   = p / HW;
        int rem = p - b * HW;
        const float* base = logits + (size_t)b * DP1 * HW + rem;
        int c0 = q * 8;
        int c1 = c0 + 8; if (c1 > DP1) c1 = DP1;   // q==15 covers 120 only
        #pragma unroll
        for (int ch = 0; ch < 8; ch++) {
            if (c0 + ch < c1)
                s += __expf(base[(size_t)(c0 + ch) * HW]);
        }
    }
    part[pl][q] = s;
    __syncthreads();
    if (q == 0 && p < NPIX) {
        float tot = 0.f;
        #pragma unroll
        for (int i = 0; i < 16; i++) tot += part[pl][i];
        g_inv[p] = 1.0f / tot;
    }
}

// ---------------------------------------------------------------------------
// K2: fused softmax-apply + frustum writer (round-10 structure, UNCHANGED:
// d-slab of 4, CG=4, __stcs, natural ~62 regs -> 4 blocks/SM; measured
// 81.4us at 5.5 TB/s effective write = at the HBM write wall), with the
// sparse 8x8 pool appended as 58 extra blocks so its ~2us hides inside the
// frustum kernel instead of serializing before it.
// ---------------------------------------------------------------------------
__global__ void __launch_bounds__(256) frustum_kernel(
    const float* __restrict__ logits,
    const float* __restrict__ img,
    const int*   __restrict__ bins,
    const float* __restrict__ dm,
    float*       __restrict__ out)
{
    if (blockIdx.x >= FRUST_BLOCKS) {
        // ---------------- sparse 8x8 average pool ----------------
        int p = (blockIdx.x - FRUST_BLOCKS) * 256 + threadIdx.x;
        if (p >= NPIX) return;
        int b   = p / HW;
        int rem = p - b * HW;
        int h   = rem / WW;
        int w   = rem - h * WW;

        const float* base = dm + ((size_t)b * HP + (size_t)h * 8) * WP + (size_t)w * 8;

        float sum = 0.f;
        float cnt = 0.f;
        #pragma unroll
        for (int i = 0; i < 8; i++) {
            const float4* row = reinterpret_cast<const float4*>(base + (size_t)i * WP);
            float4 v0 = row[0];
            float4 v1 = row[1];
            sum += (v0.x + v0.y) + (v0.z + v0.w) + (v1.x + v1.y) + (v1.z + v1.w);
            cnt += (v0.x != 0.f) + (v0.y != 0.f) + (v0.z != 0.f) + (v0.w != 0.f)
                 + (v1.x != 0.f) + (v1.y != 0.f) + (v1.z != 0.f) + (v1.w != 0.f);
        }
        float a  = sum * (1.0f / 64.0f);
        float bf = cnt * (1.0f / 64.0f);
        out[2 * (size_t)NFF + p] = a / (bf + 1e-10f);
        return;
    }

    // ---------------- frustum writer ----------------
    unsigned idx = blockIdx.x * blockDim.x + threadIdx.x;
    unsigned p4 = idx % QW;
    unsigned r  = idx / QW;
    unsigned dq = r % DQ;
    r /= DQ;
    unsigned cg = r % CG;
    unsigned b  = r / CG;
    if (b >= BB) return;
    int d0 = dq * 4;
    int c0 = cg * CPG;

    // Per-pixel inverse denominators and target bins.
    float4 I  = ((const float4*)g_inv)[(size_t)b * QW + p4];
    int4   bn = ((const int4*)bins)[(size_t)b * QW + p4];

    // Probs for the 4x4 (d, pixel) tile, computed in registers.
    float4 P[4];
    #pragma unroll
    for (int j = 0; j < 4; j++) {
        float4 L = ((const float4*)logits)[((size_t)b * DP1 + d0 + j) * QW + p4];
        P[j].x = __expf(L.x) * I.x;
        P[j].y = __expf(L.y) * I.y;
        P[j].z = __expf(L.z) * I.z;
        P[j].w = __expf(L.w) * I.w;
    }

    const float4* ig = (const float4*)img + ((size_t)b * CC + c0) * QW + p4;
    float4* ob = (float4*)out + (((size_t)b * CC + c0) * DD + d0) * QW + p4;
    const size_t cstride = (size_t)DD * QW;
    const size_t osplit  = (size_t)NFF / 4;

    #pragma unroll 2
    for (int c = 0; c < CPG; c++) {
        float4 iv = ig[(size_t)c * QW];
        float4* o1 = ob + (size_t)c * cstride;
        float4* o2 = o1 + osplit;
        #pragma unroll
        for (int j = 0; j < 4; j++) {
            int d = d0 + j;
            float4 a;
            a.x = iv.x * P[j].x; a.y = iv.y * P[j].y;
            a.z = iv.z * P[j].z; a.w = iv.w * P[j].w;
            float4 t;
            t.x = (d == bn.x) ? iv.x : 0.0f;
            t.y = (d == bn.y) ? iv.y : 0.0f;
            t.z = (d == bn.z) ? iv.z : 0.0f;
            t.w = (d == bn.w) ? iv.w : 0.0f;
            __stcs(&o1[(size_t)j * QW], a);
            __stcs(&o2[(size_t)j * QW], t);
        }
    }
}

// ---------------------------------------------------------------------------
// Launch contract
// Inputs: image_features f32, depth_logits f32, depth_maps f32,
//         depth_target_bin i32
// Output: [frustum_features | frustum_features_target | pooled_depth] f32
// ---------------------------------------------------------------------------
extern "C" void kernel_launch(void* const* d_in, const int* in_sizes, int n_in,
                              void* d_out, int out_size) {
    const float* image_features   = (const float*)d_in[0];
    const float* depth_logits     = (const float*)d_in[1];
    const float* depth_maps       = (const float*)d_in[2];
    const int*   depth_target_bin = (const int*)d_in[3];
    float* out = (float*)d_out;

    // Softmax denominators (the only serial dependency of the main kernel).
    denom_kernel<<<DENOM_BLOCKS, 512>>>(depth_logits);

    // Fused frustum writer + sparse pool.
    frustum_kernel<<<MAIN_BLOCKS, 256>>>(depth_logits, image_features,
                                         depth_target_bin, depth_maps, out);
}

// round 12
// speedup vs baseline: 1.4341x; 1.0015x over previous
#include <cuda_runtime.h>

// Problem constants (fixed shapes from reference setup_inputs)
#define BB   2
#define CC   32
#define HH   47
#define WW   156
#define DD   120
#define DP1  121              // D+1 softmax channels
#define HW   (HH * WW)        // 7332
#define QW   (HW / 4)         // 1833 float4s per (h,w) plane
#define NPIX (BB * HW)        // 14664
#define NFF  (BB * CC * DD * HW)  // 56,309,760 elements per frustum tensor
#define HP   (HH * 8)         // 376
#define WP   (WW * 8)         // 1248
#define DQ   (DD / 4)         // 30 d-slabs of 4
#define CG   4                // c-groups: best measured config (81.4us)
#define CPG  (CC / CG)        // 8 channels per group

#define DENOM_BLOCKS ((NPIX + 31) / 32)            // 459 (32 pixels/block)

// Frustum+pool fused launch: frustum blocks first, pool blocks appended.
#define FRUST_BLOCKS ((BB * CG * DQ * QW + 255) / 256)  // 1719
#define POOL_BLOCKS  ((NPIX + 255) / 256)               // 58
#define MAIN_BLOCKS  (FRUST_BLOCKS + POOL_BLOCKS)       // 1777

// Scratch: per-pixel inverse softmax denominators (59 KB).
__device__ float g_inv[NPIX];

// ---------------------------------------------------------------------------
// K1: softmax denominators. Triggers programmatic launch completion so the
// main kernel (PDL secondary) can begin its preamble while this runs.
// ---------------------------------------------------------------------------
__global__ void __launch_bounds__(512) denom_kernel(
    const float* __restrict__ logits)
{
    __shared__ float part[32][16];
    int t  = threadIdx.x;
    int pl = t & 31;           // pixel within block
    int q  = t >> 5;           // channel-chunk 0..15
    int p  = blockIdx.x * 32 + pl;

    float s = 0.f;
    if (p < NPIX) {
        int b   = p / HW;
        int rem = p - b * HW;
        const float* base = logits + (size_t)b * DP1 * HW + rem;
        int c0 = q * 8;
        int c1 = c0 + 8; if (c1 > DP1) c1 = DP1;   // q==15 covers 120 only
        #pragma unroll
        for (int ch = 0; ch < 8; ch++) {
            if (c0 + ch < c1)
                s += __expf(base[(size_t)(c0 + ch) * HW]);
        }
    }
    part[pl][q] = s;
    __syncthreads();
    if (q == 0 && p < NPIX) {
        float tot = 0.f;
        #pragma unroll
        for (int i = 0; i < 16; i++) tot += part[pl][i];
        g_inv[p] = 1.0f / tot;
    }
#if __CUDA_ARCH__ >= 900
    cudaTriggerProgrammaticLaunchCompletion();
#endif
}

// ---------------------------------------------------------------------------
// K2: fused softmax-apply + frustum writer + pool (PDL secondary).
// Store-loop structure identical to the 81.4us round-10 config (d-slab of 4,
// CG=4, __stcs, natural ~62 regs). Preamble (index math, bins load, logits
// loads, 16x __expf) runs BEFORE cudaGridDependencySynchronize(), overlapping
// the denom kernel; only the g_inv read and the final scale happen after.
// Pool blocks have no denom dependency and skip the sync.
// ---------------------------------------------------------------------------
__global__ void __launch_bounds__(256) frustum_kernel(
    const float* __restrict__ logits,
    const float* __restrict__ img,
    const int*   __restrict__ bins,
    const float* __restrict__ dm,
    float*       __restrict__ out)
{
    if (blockIdx.x >= FRUST_BLOCKS) {
        // ---------------- sparse 8x8 average pool (independent) ----------------
        int p = (blockIdx.x - FRUST_BLOCKS) * 256 + threadIdx.x;
        if (p >= NPIX) return;
        int b   = p / HW;
        int rem = p - b * HW;
        int h   = rem / WW;
        int w   = rem - h * WW;

        const float* base = dm + ((size_t)b * HP + (size_t)h * 8) * WP + (size_t)w * 8;

        float sum = 0.f;
        float cnt = 0.f;
        #pragma unroll
        for (int i = 0; i < 8; i++) {
            const float4* row = reinterpret_cast<const float4*>(base + (size_t)i * WP);
            float4 v0 = row[0];
            float4 v1 = row[1];
            sum += (v0.x + v0.y) + (v0.z + v0.w) + (v1.x + v1.y) + (v1.z + v1.w);
            cnt += (v0.x != 0.f) + (v0.y != 0.f) + (v0.z != 0.f) + (v0.w != 0.f)
                 + (v1.x != 0.f) + (v1.y != 0.f) + (v1.z != 0.f) + (v1.w != 0.f);
        }
        float a  = sum * (1.0f / 64.0f);
        float bf = cnt * (1.0f / 64.0f);
        out[2 * (size_t)NFF + p] = a / (bf + 1e-10f);
        return;
    }

    // ---------------- frustum writer ----------------
    unsigned idx = blockIdx.x * blockDim.x + threadIdx.x;
    unsigned p4 = idx % QW;
    unsigned r  = idx / QW;
    unsigned dq = r % DQ;
    r /= DQ;
    unsigned cg = r % CG;
    unsigned b  = r / CG;
    if (b >= BB) return;
    int d0 = dq * 4;
    int c0 = cg * CPG;

    // --- pre-sync preamble: everything that doesn't need g_inv ---
    int4 bn = ((const int4*)bins)[(size_t)b * QW + p4];

    float4 E[4];   // unnormalized exp(logits) tile
    #pragma unroll
    for (int j = 0; j < 4; j++) {
        float4 L = ((const float4*)logits)[((size_t)b * DP1 + d0 + j) * QW + p4];
        E[j].x = __expf(L.x);
        E[j].y = __expf(L.y);
        E[j].z = __expf(L.z);
        E[j].w = __expf(L.w);
    }

#if __CUDA_ARCH__ >= 900
    cudaGridDependencySynchronize();   // wait for denom_kernel results
#endif

    float4 I = ((const float4*)g_inv)[(size_t)b * QW + p4];
    float4 P[4];
    #pragma unroll
    for (int j = 0; j < 4; j++) {
        P[j].x = E[j].x * I.x;
        P[j].y = E[j].y * I.y;
        P[j].z = E[j].z * I.z;
        P[j].w = E[j].w * I.w;
    }

    const float4* ig = (const float4*)img + ((size_t)b * CC + c0) * QW + p4;
    float4* ob = (float4*)out + (((size_t)b * CC + c0) * DD + d0) * QW + p4;
    const size_t cstride = (size_t)DD * QW;
    const size_t osplit  = (size_t)NFF / 4;

    #pragma unroll 2
    for (int c = 0; c < CPG; c++) {
        float4 iv = ig[(size_t)c * QW];
        float4* o1 = ob + (size_t)c * cstride;
        float4* o2 = o1 + osplit;
        #pragma unroll
        for (int j = 0; j < 4; j++) {
            int d = d0 + j;
            float4 a;
            a.x = iv.x * P[j].x; a.y = iv.y * P[j].y;
            a.z = iv.z * P[j].z; a.w = iv.w * P[j].w;
            float4 t;
            t.x = (d == bn.x) ? iv.x : 0.0f;
            t.y = (d == bn.y) ? iv.y : 0.0f;
            t.z = (d == bn.z) ? iv.z : 0.0f;
            t.w = (d == bn.w) ? iv.w : 0.0f;
            __stcs(&o1[(size_t)j * QW], a);
            __stcs(&o2[(size_t)j * QW], t);
        }
    }
}

// ---------------------------------------------------------------------------
// Launch contract
// Inputs: image_features f32, depth_logits f32, depth_maps f32,
//         depth_target_bin i32
// Output: [frustum_features | frustum_features_target | pooled_depth] f32
// ---------------------------------------------------------------------------
extern "C" void kernel_launch(void* const* d_in, const int* in_sizes, int n_in,
                              void* d_out, int out_size) {
    const float* image_features   = (const float*)d_in[0];
    const float* depth_logits     = (const float*)d_in[1];
    const float* depth_maps       = (const float*)d_in[2];
    const int*   depth_target_bin = (const int*)d_in[3];
    float* out = (float*)d_out;

    // Primary: softmax denominators.
    denom_kernel<<<DENOM_BLOCKS, 512>>>(depth_logits);

    // Secondary: fused frustum writer + pool, launched with PDL so its
    // preamble overlaps denom_kernel. Captured as a programmatic graph edge.
    {
        cudaLaunchConfig_t cfg = {};
        cfg.gridDim  = dim3(MAIN_BLOCKS, 1, 1);
        cfg.blockDim = dim3(256, 1, 1);
        cfg.dynamicSmemBytes = 0;
        cfg.stream = 0;   // legacy default stream (same as <<<>>>)

        cudaLaunchAttribute attrs[1];
        attrs[0].id = cudaLaunchAttributeProgrammaticStreamSerialization;
        attrs[0].val.programmaticStreamSerializationAllowed = 1;
        cfg.attrs    = attrs;
        cfg.numAttrs = 1;

        cudaLaunchKernelEx(&cfg, frustum_kernel,
                           depth_logits, image_features,
                           depth_target_bin, depth_maps, out);
    }
}

// round 14
// speedup vs baseline: 1.4456x; 1.0080x over previous
#include <cuda_runtime.h>

// Problem constants (fixed shapes from reference setup_inputs)
#define BB   2
#define CC   32
#define HH   47
#define WW   156
#define DD   120
#define DP1  121              // D+1 softmax channels
#define HW   (HH * WW)        // 7332
#define QW   (HW / 4)         // 1833 float4s per (h,w) plane
#define NPIX (BB * HW)        // 14664
#define NFF  (BB * CC * DD * HW)  // 56,309,760 elements per frustum tensor
#define HP   (HH * 8)         // 376
#define WP   (WW * 8)         // 1248
#define DQ   (DD / 4)         // 30 d-slabs of 4
#define CG   4                // c-groups: best measured config (81.4us)
#define CPG  (CC / CG)        // 8 channels per group

#define DENOM_BLOCKS ((NPIX + 31) / 32)            // 459 (32 pixels/block)

// Frustum+pool fused launch: frustum blocks first, pool blocks appended.
#define FRUST_BLOCKS ((BB * CG * DQ * QW + 255) / 256)  // 1719
#define POOL_BLOCKS  ((NPIX + 255) / 256)               // 58
#define MAIN_BLOCKS  (FRUST_BLOCKS + POOL_BLOCKS)       // 1777

// Scratch: per-pixel inverse softmax denominators (59 KB).
__device__ float g_inv[NPIX];

// ---------------------------------------------------------------------------
// K1: softmax denominators (at the read roofline: 14 MB / ~2.2us).
// Triggers programmatic launch completion for the PDL secondary.
// ---------------------------------------------------------------------------
__global__ void __launch_bounds__(512) denom_kernel(
    const float* __restrict__ logits)
{
    __shared__ float part[32][16];
    int t  = threadIdx.x;
    int pl = t & 31;           // pixel within block
    int q  = t >> 5;           // channel-chunk 0..15
    int p  = blockIdx.x * 32 + pl;

    float s = 0.f;
    if (p < NPIX) {
        int b   = p / HW;
        int rem = p - b * HW;
        const float* base = logits + (size_t)b * DP1 * HW + rem;
        int c0 = q * 8;
        int c1 = c0 + 8; if (c1 > DP1) c1 = DP1;   // q==15 covers 120 only
        #pragma unroll
        for (int ch = 0; ch < 8; ch++) {
            if (c0 + ch < c1)
                s += __expf(base[(size_t)(c0 + ch) * HW]);
        }
    }
    part[pl][q] = s;
    __syncthreads();
    if (q == 0 && p < NPIX) {
        float tot = 0.f;
        #pragma unroll
        for (int i = 0; i < 16; i++) tot += part[pl][i];
        g_inv[p] = 1.0f / tot;
    }
#if __CUDA_ARCH__ >= 900
    cudaTriggerProgrammaticLaunchCompletion();
#endif
}

// ---------------------------------------------------------------------------
// K2 (PDL secondary): fused frustum writer + pool, TWO-PASS structure.
// Pass 1 (pre-sync): all target-tensor stores (need only bins + img) —
//   a wide overlap window (~tens of us for wave-1 blocks) that fully hides
//   the 2.2us denom kernel.
// Pass 2 (post-sync): read g_inv, compute the 4x4 probs tile, write out1.
// Store-loop shape per pass matches the wall-limited 81.4us config
// (d-slab of 4, CG=4, __stcs, contiguous STG.128 bursts).
// ---------------------------------------------------------------------------
__global__ void __launch_bounds__(256) frustum_kernel(
    const float* __restrict__ logits,
    const float* __restrict__ img,
    const int*   __restrict__ bins,
    const float* __restrict__ dm,
    float*       __restrict__ out)
{
    if (blockIdx.x >= FRUST_BLOCKS) {
        // ---------------- sparse 8x8 average pool (independent) ----------------
        int p = (blockIdx.x - FRUST_BLOCKS) * 256 + threadIdx.x;
        if (p >= NPIX) return;
        int b   = p / HW;
        int rem = p - b * HW;
        int h   = rem / WW;
        int w   = rem - h * WW;

        const float* base = dm + ((size_t)b * HP + (size_t)h * 8) * WP + (size_t)w * 8;

        float sum = 0.f;
        float cnt = 0.f;
        #pragma unroll
        for (int i = 0; i < 8; i++) {
            const float4* row = reinterpret_cast<const float4*>(base + (size_t)i * WP);
            float4 v0 = row[0];
            float4 v1 = row[1];
            sum += (v0.x + v0.y) + (v0.z + v0.w) + (v1.x + v1.y) + (v1.z + v1.w);
            cnt += (v0.x != 0.f) + (v0.y != 0.f) + (v0.z != 0.f) + (v0.w != 0.f)
                 + (v1.x != 0.f) + (v1.y != 0.f) + (v1.z != 0.f) + (v1.w != 0.f);
        }
        float a  = sum * (1.0f / 64.0f);
        float bf = cnt * (1.0f / 64.0f);
        out[2 * (size_t)NFF + p] = a / (bf + 1e-10f);
        return;
    }

    // ---------------- frustum writer ----------------
    unsigned idx = blockIdx.x * blockDim.x + threadIdx.x;
    unsigned p4 = idx % QW;
    unsigned r  = idx / QW;
    unsigned dq = r % DQ;
    r /= DQ;
    unsigned cg = r % CG;
    unsigned b  = r / CG;
    if (b >= BB) return;
    int d0 = dq * 4;
    int c0 = cg * CPG;

    const float4* ig = (const float4*)img + ((size_t)b * CC + c0) * QW + p4;
    float4* ob = (float4*)out + (((size_t)b * CC + c0) * DD + d0) * QW + p4;
    const size_t cstride = (size_t)DD * QW;
    const size_t osplit  = (size_t)NFF / 4;

    // ---- Pass 1 (pre-sync): target tensor — no g_inv dependency ----
    int4 bn = ((const int4*)bins)[(size_t)b * QW + p4];

    #pragma unroll 2
    for (int c = 0; c < CPG; c++) {
        float4 iv = ig[(size_t)c * QW];
        float4* o2 = ob + (size_t)c * cstride + osplit;
        #pragma unroll
        for (int j = 0; j < 4; j++) {
            int d = d0 + j;
            float4 t;
            t.x = (d == bn.x) ? iv.x : 0.0f;
            t.y = (d == bn.y) ? iv.y : 0.0f;
            t.z = (d == bn.z) ? iv.z : 0.0f;
            t.w = (d == bn.w) ? iv.w : 0.0f;
            __stcs(&o2[(size_t)j * QW], t);
        }
    }

#if __CUDA_ARCH__ >= 900
    cudaGridDependencySynchronize();   // denom results now needed
#endif

    // ---- Pass 2 (post-sync): softmax-apply + frustum_features ----
    float4 I = ((const float4*)g_inv)[(size_t)b * QW + p4];
    float4 P[4];
    #pragma unroll
    for (int j = 0; j < 4; j++) {
        float4 L = ((const float4*)logits)[((size_t)b * DP1 + d0 + j) * QW + p4];
        P[j].x = __expf(L.x) * I.x;
        P[j].y = __expf(L.y) * I.y;
        P[j].z = __expf(L.z) * I.z;
        P[j].w = __expf(L.w) * I.w;
    }

    #pragma unroll 2
    for (int c = 0; c < CPG; c++) {
        float4 iv = ig[(size_t)c * QW];
        float4* o1 = ob + (size_t)c * cstride;
        #pragma unroll
        for (int j = 0; j < 4; j++) {
            float4 a;
            a.x = iv.x * P[j].x; a.y = iv.y * P[j].y;
            a.z = iv.z * P[j].z; a.w = iv.w * P[j].w;
            __stcs(&o1[(size_t)j * QW], a);
        }
    }
}

// ---------------------------------------------------------------------------
// Launch contract
// Inputs: image_features f32, depth_logits f32, depth_maps f32,
//         depth_target_bin i32
// Output: [frustum_features | frustum_features_target | pooled_depth] f32
// ---------------------------------------------------------------------------
extern "C" void kernel_launch(void* const* d_in, const int* in_sizes, int n_in,
                              void* d_out, int out_size) {
    const float* image_features   = (const float*)d_in[0];
    const float* depth_logits     = (const float*)d_in[1];
    const float* depth_maps       = (const float*)d_in[2];
    const int*   depth_target_bin = (const int*)d_in[3];
    float* out = (float*)d_out;

    // Primary: softmax denominators.
    denom_kernel<<<DENOM_BLOCKS, 512>>>(depth_logits);

    // Secondary: fused frustum writer + pool with PDL; its pass-1 target
    // stores give denom a wide window to overlap into.
    {
        cudaLaunchConfig_t cfg = {};
        cfg.gridDim  = dim3(MAIN_BLOCKS, 1, 1);
        cfg.blockDim = dim3(256, 1, 1);
        cfg.dynamicSmemBytes = 0;
        cfg.stream = 0;   // legacy default stream (same as <<<>>>)

        cudaLaunchAttribute attrs[1];
        attrs[0].id = cudaLaunchAttributeProgrammaticStreamSerialization;
        attrs[0].val.programmaticStreamSerializationAllowed = 1;
        cfg.attrs    = attrs;
        cfg.numAttrs = 1;

        cudaLaunchKernelEx(&cfg, frustum_kernel,
                           depth_logits, image_features,
                           depth_target_bin, depth_maps, out);
    }
}

// round 15
// speedup vs baseline: 1.5406x; 1.0657x over previous
#include <cuda_runtime.h>

// Problem constants (fixed shapes from reference setup_inputs)
#define BB   2
#define CC   32
#define HH   47
#define WW   156
#define DD   120
#define DP1  121              // D+1 softmax channels
#define HW   (HH * WW)        // 7332
#define QW   (HW / 4)         // 1833 float4s per (h,w) plane
#define NPIX (BB * HW)        // 14664
#define NFF  (BB * CC * DD * HW)  // 56,309,760 elements per frustum tensor
#define HP   (HH * 8)         // 376
#define WP   (WW * 8)         // 1248
#define DQ   (DD / 4)         // 30 d-slabs of 4
#define CG   4                // c-groups: wall-limited best config
#define CPG  (CC / CG)        // 8 channels per group

// Single-kernel grid layout: [denom | frustum | pool]
#define DENOM_BLOCKS ((NPIX + 31) / 32)                 // 459 (32 px/block)
#define FRUST_BLOCKS ((BB * CG * DQ * QW + 255) / 256)  // 1719
#define POOL_BLOCKS  ((NPIX + 255) / 256)               // 58
#define ALL_BLOCKS   (DENOM_BLOCKS + FRUST_BLOCKS + POOL_BLOCKS)  // 2236

// Scratch: per-pixel inverse softmax denominators + decoupled-flag counters.
__device__ float g_inv[NPIX];
__device__ volatile int g_done;      // denom blocks completed (self-resets)
__device__ int          g_consumed;  // frustum blocks past the wait

// ---------------------------------------------------------------------------
// Single fused kernel. Block role by blockIdx.x:
//  [0, DENOM): softmax denominators -> g_inv, then signal g_done.
//     All 459 denom blocks fit in scheduling wave 1 (459 < ~740 resident
//     slots) and are dispatched first => signal always arrives; no deadlock.
//  [DENOM, DENOM+FRUST): two-pass frustum writer. Pass 1 = target-tensor
//     stores (no g_inv needed, ~40us of overlap budget). Then thread 0 spins
//     on g_done (denom finishes in ~3us, fully hidden), barrier, pass 2 =
//     softmax-apply + frustum_features stores. Last block resets counters
//     so every graph replay starts clean.
//  [DENOM+FRUST, ...): independent sparse 8x8 pool.
// ---------------------------------------------------------------------------
__global__ void __launch_bounds__(256) fused_kernel(
    const float* __restrict__ logits,
    const float* __restrict__ img,
    const int*   __restrict__ bins,
    const float* __restrict__ dm,
    float*       __restrict__ out)
{
    int t = threadIdx.x;

    if (blockIdx.x < DENOM_BLOCKS) {
        // ---------------- softmax denominators ----------------
        __shared__ float part[32][8];
        int pl = t & 31;           // pixel within block
        int q  = t >> 5;           // channel-chunk 0..7 (16 channels each)
        int p  = blockIdx.x * 32 + pl;

        float s = 0.f;
        if (p < NPIX) {
            int b   = p / HW;
            int rem = p - b * HW;
            const float* base = logits + (size_t)b * DP1 * HW + rem;
            int c0 = q * 16;
            int c1 = c0 + 16; if (c1 > DP1) c1 = DP1;   // q==7: 112..120
            #pragma unroll
            for (int ch = 0; ch < 16; ch++) {
                if (c0 + ch < c1)
                    s += __expf(base[(size_t)(c0 + ch) * HW]);
            }
        }
        part[pl][q] = s;
        __syncthreads();
        if (q == 0 && p < NPIX) {
            float tot = 0.f;
            #pragma unroll
            for (int i = 0; i < 8; i++) tot += part[pl][i];
            g_inv[p] = 1.0f / tot;
            __threadfence();       // make g_inv visible device-wide
        }
        __syncthreads();
        if (t == 0)
            atomicAdd((int*)&g_done, 1);
        return;
    }

    if (blockIdx.x >= DENOM_BLOCKS + FRUST_BLOCKS) {
        // ---------------- sparse 8x8 average pool (independent) ----------------
        int p = (blockIdx.x - DENOM_BLOCKS - FRUST_BLOCKS) * 256 + t;
        if (p >= NPIX) return;
        int b   = p / HW;
        int rem = p - b * HW;
        int h   = rem / WW;
        int w   = rem - h * WW;

        const float* base = dm + ((size_t)b * HP + (size_t)h * 8) * WP + (size_t)w * 8;

        float sum = 0.f;
        float cnt = 0.f;
        #pragma unroll
        for (int i = 0; i < 8; i++) {
            const float4* row = reinterpret_cast<const float4*>(base + (size_t)i * WP);
            float4 v0 = row[0];
            float4 v1 = row[1];
            sum += (v0.x + v0.y) + (v0.z + v0.w) + (v1.x + v1.y) + (v1.z + v1.w);
            cnt += (v0.x != 0.f) + (v0.y != 0.f) + (v0.z != 0.f) + (v0.w != 0.f)
                 + (v1.x != 0.f) + (v1.y != 0.f) + (v1.z != 0.f) + (v1.w != 0.f);
        }
        float a  = sum * (1.0f / 64.0f);
        float bf = cnt * (1.0f / 64.0f);
        out[2 * (size_t)NFF + p] = a / (bf + 1e-10f);
        return;
    }

    // ---------------- frustum writer (two-pass) ----------------
    unsigned idx = (blockIdx.x - DENOM_BLOCKS) * blockDim.x + t;
    unsigned p4 = idx % QW;
    unsigned r  = idx / QW;
    unsigned dq = r % DQ;
    r /= DQ;
    unsigned cg = r % CG;
    unsigned b  = r / CG;
    bool valid = (b < BB);

    int d0 = dq * 4;
    int c0 = cg * CPG;

    const float4* ig = (const float4*)img + ((size_t)b * CC + c0) * QW + p4;
    float4* ob = (float4*)out + (((size_t)b * CC + c0) * DD + d0) * QW + p4;
    const size_t cstride = (size_t)DD * QW;
    const size_t osplit  = (size_t)NFF / 4;

    // ---- Pass 1: target tensor (no g_inv dependency) ----
    if (valid) {
        int4 bn = ((const int4*)bins)[(size_t)b * QW + p4];
        #pragma unroll 2
        for (int c = 0; c < CPG; c++) {
            float4 iv = ig[(size_t)c * QW];
            float4* o2 = ob + (size_t)c * cstride + osplit;
            #pragma unroll
            for (int j = 0; j < 4; j++) {
                int d = d0 + j;
                float4 tg;
                tg.x = (d == bn.x) ? iv.x : 0.0f;
                tg.y = (d == bn.y) ? iv.y : 0.0f;
                tg.z = (d == bn.z) ? iv.z : 0.0f;
                tg.w = (d == bn.w) ? iv.w : 0.0f;
                __stcs(&o2[(size_t)j * QW], tg);
            }
        }
    }

    // ---- Wait for denom blocks (usually already done) ----
    if (t == 0) {
        while (g_done < DENOM_BLOCKS) { __nanosleep(64); }
        __threadfence();   // acquire: g_inv writes now visible
    }
    __syncthreads();

    // ---- Pass 2: softmax-apply + frustum_features ----
    if (valid) {
        float4 I = ((const float4*)g_inv)[(size_t)b * QW + p4];
        float4 P[4];
        #pragma unroll
        for (int j = 0; j < 4; j++) {
            float4 L = ((const float4*)logits)[((size_t)b * DP1 + d0 + j) * QW + p4];
            P[j].x = __expf(L.x) * I.x;
            P[j].y = __expf(L.y) * I.y;
            P[j].z = __expf(L.z) * I.z;
            P[j].w = __expf(L.w) * I.w;
        }

        #pragma unroll 2
        for (int c = 0; c < CPG; c++) {
            float4 iv = ig[(size_t)c * QW];
            float4* o1 = ob + (size_t)c * cstride;
            #pragma unroll
            for (int j = 0; j < 4; j++) {
                float4 a;
                a.x = iv.x * P[j].x; a.y = iv.y * P[j].y;
                a.z = iv.z * P[j].z; a.w = iv.w * P[j].w;
                __stcs(&o1[(size_t)j * QW], a);
            }
        }
    }

    // ---- Counter self-reset so graph replays start clean ----
    if (t == 0) {
        int old = atomicAdd(&g_consumed, 1);
        if (old == FRUST_BLOCKS - 1) {   // last frustum block: all have passed the wait
            g_done = 0;
            g_consumed = 0;
        }
    }
}

// ---------------------------------------------------------------------------
// Launch contract
// Inputs: image_features f32, depth_logits f32, depth_maps f32,
//         depth_target_bin i32
// Output: [frustum_features | frustum_features_target | pooled_depth] f32
// ---------------------------------------------------------------------------
extern "C" void kernel_launch(void* const* d_in, const int* in_sizes, int n_in,
                              void* d_out, int out_size) {
    const float* image_features   = (const float*)d_in[0];
    const float* depth_logits     = (const float*)d_in[1];
    const float* depth_maps       = (const float*)d_in[2];
    const int*   depth_target_bin = (const int*)d_in[3];
    float* out = (float*)d_out;

    fused_kernel<<<ALL_BLOCKS, 256>>>(depth_logits, image_features,
                                      depth_target_bin, depth_maps, out);
}